// round 9
// baseline (speedup 1.0000x reference)
#include <cuda_runtime.h>
#include <cuda_fp16.h>

#define NN 1024
#define BB 4
#define HH 32

// 2 MB scratch: adjacency in f16, pre-paired {A[i][16t+g], A[i][16t+g+8]}.
__device__ __half2 g_Ah[NN * NN / 2];

// ---------------- f16x2 helpers ----------------
static __device__ __forceinline__ unsigned packh2(float lo, float hi) {
    unsigned r;  // first PTX source -> upper half
    asm("cvt.rn.f16x2.f32 %0, %1, %2;" : "=r"(r) : "f"(hi), "f"(lo));
    return r;
}
static __device__ __forceinline__ unsigned tanh_h2(unsigned v) {
    unsigned r;
    asm("tanh.approx.f16x2 %0, %1;" : "=r"(r) : "r"(v));
    return r;
}
static __device__ __forceinline__ unsigned hfma2(unsigned a, unsigned b, unsigned c) {
    unsigned d;
    asm("fma.rn.f16x2 %0, %1, %2, %3;" : "=r"(d) : "r"(a), "r"(b), "r"(c));
    return d;
}
static __device__ __forceinline__ unsigned hadd2(unsigned a, unsigned b) {
    unsigned d;
    asm("add.rn.f16x2 %0, %1, %2;" : "=r"(d) : "r"(a), "r"(b));
    return d;
}
static __device__ __forceinline__ unsigned hmul2(unsigned a, unsigned b) {
    unsigned d;
    asm("mul.rn.f16x2 %0, %1, %2;" : "=r"(d) : "r"(a), "r"(b));
    return d;
}
static __device__ __forceinline__ unsigned prmt5410(unsigned a, unsigned b) {
    unsigned d;  // {lo: a.lo16, hi: b.lo16}
    asm("prmt.b32 %0, %1, %2, 0x5410;" : "=r"(d) : "r"(a), "r"(b));
    return d;
}
static __device__ __forceinline__ float hlo(unsigned v) {
    float f;
    asm("{.reg .f16 l,h; mov.b32 {l,h}, %1; cvt.f32.f16 %0, l;}" : "=f"(f) : "r"(v));
    return f;
}
static __device__ __forceinline__ float hhi(unsigned v) {
    float f;
    asm("{.reg .f16 l,h; mov.b32 {l,h}, %1; cvt.f32.f16 %0, h;}" : "=f"(f) : "r"(v));
    return f;
}
// D(f16) = A(m16k16 f16) * B(k16n8 f16) + C(f16), separate C operand.
static __device__ __forceinline__ void mma_f16h_c(
    unsigned& d0, unsigned& d1,
    unsigned a0, unsigned a1, unsigned a2, unsigned a3,
    unsigned b0, unsigned b1, unsigned c0, unsigned c1) {
    asm("mma.sync.aligned.m16n8k16.row.col.f16.f16.f16.f16 "
        "{%0,%1},{%2,%3,%4,%5},{%6,%7},{%8,%9};"
        : "=r"(d0), "=r"(d1)
        : "r"(a0), "r"(a1), "r"(a2), "r"(a3), "r"(b0), "r"(b1),
          "r"(c0), "r"(c1));
}

#define ONE2 0x3C003C00u   // {1.0h, 1.0h}
#define HALF2 0x38003800u  // {0.5h, 0.5h}

// ---------------- Kernel 1: masked row softmax of Theta -> g_Ah ----------------
__global__ __launch_bounds__(256) void softmax_kernel(const float* __restrict__ Theta) {
    int i = blockIdx.x;
    int t = threadIdx.x;
    const float* row = Theta + (size_t)i * NN;

    float vals[4];
    float m = -3.4e38f;
#pragma unroll
    for (int u = 0; u < 4; u++) {
        vals[u] = row[t + 256 * u];
        m = fmaxf(m, vals[u]);
    }
#pragma unroll
    for (int o = 16; o; o >>= 1) m = fmaxf(m, __shfl_xor_sync(0xffffffffu, m, o));

    __shared__ float redmax[8], redsum[8];
    if ((t & 31) == 0) redmax[t >> 5] = m;
    __syncthreads();
    float m0 = redmax[0];
#pragma unroll
    for (int w = 1; w < 8; w++) m0 = fmaxf(m0, redmax[w]);

    float s = 0.f;
#pragma unroll
    for (int u = 0; u < 4; u++) {
        int j = t + 256 * u;
        float e = __expf(vals[u] - m0);
        if (j == i) e = 0.f;
        vals[u] = e;
        s += e;
    }
#pragma unroll
    for (int o = 16; o; o >>= 1) s += __shfl_xor_sync(0xffffffffu, s, o);
    if ((t & 31) == 0) redsum[t >> 5] = s;
    __syncthreads();
    float tot = 0.f;
#pragma unroll
    for (int w = 0; w < 8; w++) tot += redsum[w];
    float inv = 1.0f / tot;
    // pre-paired f16 store: half index = i*NN + (j>>4)*16 + 2*(j&7) + ((j&15)>>3)
    __half* Ah = reinterpret_cast<__half*>(g_Ah);
#pragma unroll
    for (int u = 0; u < 4; u++) {
        int j = t + 256 * u;
        size_t idx = (size_t)i * NN + ((j >> 4) << 4) + ((j & 7) << 1) + ((j & 15) >> 3);
        Ah[idx] = __float2half(vals[u] * inv);
    }
}

// ---------------- Kernel 2: pairwise MLP, all GEMMs on tensor pipe ----------------
// One block per (b-pair, i): grid 2048. Separate-C MMAs (no accumulator init),
// parallel k-half chains merged with HADD2, f16 layer-3 + PRMT alpha path.
__global__ __launch_bounds__(256, 4) void agg_kernel(
    const float* __restrict__ x,
    const float* __restrict__ W1, const float* __restrict__ b1,
    const float* __restrict__ W2, const float* __restrict__ b2,
    const float* __restrict__ W3, const float* __restrict__ b3,
    float* __restrict__ out) {
    __shared__ float sX[2][NN];        // x rows for both batches
    __shared__ unsigned sXh[2][NN];    // pre-packed f16x2 {x,x}
    __shared__ float sc0[2][HH];       // per-b: (W1[k][0]-W1[k][2])*xi + b1[k]
    __shared__ float sw12[HH];         // W1[k][1]+W1[k][2]
    __shared__ float warpsum[2][8];

    int t = threadIdx.x;
    int lane = t & 31, warp = t >> 5;
    int g = lane >> 2;   // groupID
    int q = lane & 3;    // threadID_in_group
    int bi = blockIdx.x;
    int b0 = (bi >> 10) << 1;          // first batch of the pair
    int i = bi & (NN - 1);
    const __half2* Arow2 = g_Ah + (size_t)i * (NN / 2);

    for (int idx = t; idx < 2 * NN; idx += 256) {
        int bl = idx >> 10, j = idx & (NN - 1);
        float v = x[(b0 + bl) * NN + j];
        sX[bl][j] = v;
        sXh[bl][j] = packh2(v, v);
    }
    if (t < HH) {
        float w0 = W1[3 * t + 0];
        float w1v = W1[3 * t + 1];
        float w2v = W1[3 * t + 2];
        float wd = w0 - w2v;
        float bb1 = b1[t];
        sc0[0][t] = fmaf(wd, x[(b0 + 0) * NN + i], bb1);
        sc0[1][t] = fmaf(wd, x[(b0 + 1) * NN + i], bb1);
        sw12[t] = w1v + w2v;
    }
    float b3v = b3[0];
    bool lead = (q == 0);

    // W2 B-fragments register-resident (f16x2), m16n8k16 col-major B layout.
    unsigned rB[2][4][2];
#pragma unroll
    for (int kt = 0; kt < 2; kt++)
#pragma unroll
        for (int nt = 0; nt < 4; nt++) {
            const float* wrow = W2 + (nt * 8 + g) * HH + kt * 16 + 2 * q;
            rB[kt][nt][0] = packh2(wrow[0], wrow[1]);
            rB[kt][nt][1] = packh2(wrow[8], wrow[9]);
        }
    // b2 as C-fragment seed for this lane's columns m = nt*8+2q, +1
    unsigned b2h[4];
#pragma unroll
    for (int nt = 0; nt < 4; nt++)
        b2h[nt] = packh2(b2[nt * 8 + 2 * q], b2[nt * 8 + 2 * q + 1]);
    // Layer-3 B-fragment: column n=0 carries W3, others zero.
    unsigned rW3[2][2];
    if (g == 0) {
        rW3[0][0] = packh2(W3[2 * q], W3[2 * q + 1]);
        rW3[0][1] = packh2(W3[2 * q + 8], W3[2 * q + 9]);
        rW3[1][0] = packh2(W3[2 * q + 16], W3[2 * q + 17]);
        rW3[1][1] = packh2(W3[2 * q + 24], W3[2 * q + 25]);
    } else {
        rW3[0][0] = rW3[0][1] = rW3[1][0] = rW3[1][1] = 0u;
    }
    // b3 as layer-3 C seed: col 0 only -> q==0 lanes' lo half.
    unsigned b3h = lead ? packh2(b3v, 0.f) : 0u;

    unsigned w12h[4];
    __syncthreads();
#pragma unroll
    for (int p = 0; p < 4; p++) {
        int k0 = 2 * q + 8 * p;
        w12h[p] = packh2(sw12[k0], sw12[k0 + 1]);
    }

    float accs[2];

#pragma unroll
    for (int bb = 0; bb < 2; bb++) {
        float xi = sX[bb][i];
        unsigned c0h[4];
#pragma unroll
        for (int p = 0; p < 4; p++) {
            int k0 = 2 * q + 8 * p;
            c0h[p] = packh2(sc0[bb][k0], sc0[bb][k0 + 1]);
        }

        float acc = 0.f;
#pragma unroll
        for (int tile = 0; tile < 8; tile++) {
            int jb = (tile * 8 + warp) * 16;
            int j1 = jb + g, j2 = jb + g + 8;
            // A pair load first; latency hides behind the MLP chain
            __half2 a2 = __ldg(Arow2 + (jb >> 1) + g);   // {A[j1], A[j2]}
            unsigned xh1 = sXh[bb][j1];
            unsigned xh2 = sXh[bb][j2];

            // Layer 1: A-fragments directly (aG = row g, aH = row g+8)
            unsigned aG[4], aH[4];
#pragma unroll
            for (int p = 0; p < 4; p++) {
                aG[p] = tanh_h2(hfma2(w12h[p], xh1, c0h[p]));
                aH[p] = tanh_h2(hfma2(w12h[p], xh2, c0h[p]));
            }

            // Layer 2: two independent k-half MMA chains, merged by HADD2.
            unsigned th1[4], th2[4];
#pragma unroll
            for (int nt = 0; nt < 4; nt++) {
                unsigned dA0, dA1, dB0, dB1;
                mma_f16h_c(dA0, dA1, aG[0], aH[0], aG[1], aH[1],
                           rB[0][nt][0], rB[0][nt][1], b2h[nt], b2h[nt]);
                mma_f16h_c(dB0, dB1, aG[2], aH[2], aG[3], aH[3],
                           rB[1][nt][0], rB[1][nt][1], 0u, 0u);
                th1[nt] = tanh_h2(hadd2(dA0, dB0));  // row g
                th2[nt] = tanh_h2(hadd2(dA1, dB1));  // row g+8
            }

            // Layer 3: two independent f16 MMAs; raw in col 0 of q==0 lanes.
            unsigned rA0, rA1, rB0_, rB1_;
            mma_f16h_c(rA0, rA1, th1[0], th2[0], th1[1], th2[1],
                       rW3[0][0], rW3[0][1], b3h, b3h);
            mma_f16h_c(rB0_, rB1_, th1[2], th2[2], th1[3], th2[3],
                       rW3[1][0], rW3[1][1], 0u, 0u);
            unsigned r0 = hadd2(rA0, rB0_);
            unsigned r1 = hadd2(rA1, rB1_);
            unsigned rawp = prmt5410(r0, r1);       // {raw_g, raw_g+8}

            // alpha = 1 + tanh(raw/2), both in one f16x2
            unsigned ah = hadd2(tanh_h2(hmul2(rawp, HALF2)), ONE2);
            float al1 = hlo(ah);
            float al2 = hhi(ah);

            float2 af = __half22float2(a2);
            float xj1 = sX[bb][j1], xj2 = sX[bb][j2];
            float c = af.x * al1 * (xj1 - xi) + af.y * al2 * (xj2 - xi);
            acc += lead ? c : 0.f;   // raw only valid on q==0 lanes
        }
        accs[bb] = acc;
    }

    // block reduction for both batches
#pragma unroll
    for (int bb = 0; bb < 2; bb++) {
        float a = accs[bb];
#pragma unroll
        for (int o = 16; o; o >>= 1) a += __shfl_xor_sync(0xffffffffu, a, o);
        if (lane == 0) warpsum[bb][warp] = a;
    }
    __syncthreads();
    if (t < 2) {
        float s = 0.f;
#pragma unroll
        for (int w = 0; w < 8; w++) s += warpsum[t][w];
        out[(b0 + t) * NN + i] = fmaf(0.1f, s, sX[t][i]);
    }
}

extern "C" void kernel_launch(void* const* d_in, const int* in_sizes, int n_in,
                              void* d_out, int out_size) {
    (void)in_sizes; (void)n_in; (void)out_size;
    const float* x  = (const float*)d_in[0];
    const float* Th = (const float*)d_in[1];
    const float* W1 = (const float*)d_in[2];
    const float* b1 = (const float*)d_in[3];
    const float* W2 = (const float*)d_in[4];
    const float* b2 = (const float*)d_in[5];
    const float* W3 = (const float*)d_in[6];
    const float* b3 = (const float*)d_in[7];
    float* out = (float*)d_out;

    softmax_kernel<<<NN, 256>>>(Th);
    agg_kernel<<<(BB / 2) * NN, 256>>>(x, W1, b1, W2, b2, W3, b3, out);
}